// round 12
// baseline (speedup 1.0000x reference)
#include <cuda_runtime.h>
#include <cuda_bf16.h>
#include <cstdint>
#include <cstddef>

#define NB 8192
#define ND 128
#define TILE 128
#define NTILE (NB / TILE)       // 64
#define NTRI 2080               // upper-triangular tiles
#define SEGJ 3
#define NSEG1 363               // sum over a of ceil((64-2a)/3)

#define KPB 272                 // row pitch in bytes: conflict-free ldmatrix
#define ATS 34816               // one 128x128 bf16 tile with pitch 272
// pass1 smem layout
#define SM_YIS 0                // 2 x 128 ints
#define SM_YJS 1024             // 128 ints
#define SM_TBL 1536             // 2 x 128 x 9 floats = 9216
#define SM_A   10752            // 4 x ATS (blk0 hi, blk0 lo, blk1 hi, blk1 lo)
#define SM_B   (SM_A + 4 * ATS) // 2 x ATS (hi, lo)
#define SMEM_TOTAL (SM_B + 2 * ATS)   // 219648 B
#define CTS 9

__device__ __align__(16) float g_S[(size_t)NTRI * TILE * TILE];  // 136 MB, tile-blocked
__device__ __align__(16) __nv_bfloat16 g_xhi[(size_t)NB * ND];
__device__ __align__(16) __nv_bfloat16 g_xlo[(size_t)NB * ND];
__device__ unsigned g_minpos[NB];
__device__ unsigned g_maxneg[NB];
__device__ int g_y[NB];
__device__ float g_psT[(size_t)NB * NTILE];   // per (row, tile) partials
__device__ float g_nsT[(size_t)NB * NTILE];
__device__ float g_row[NB];
__device__ int   g_valid[NB];
__device__ int   g_is64;

// ---------------- helpers ----------------
__device__ __forceinline__ uint32_t smem_u32(const void* p) {
    uint32_t a;
    asm("{ .reg .u64 t; cvta.to.shared.u64 t, %1; cvt.u32.u64 %0, t; }" : "=r"(a) : "l"(p));
    return a;
}
__device__ __forceinline__ void ldsm4(uint32_t& r0, uint32_t& r1, uint32_t& r2, uint32_t& r3,
                                      uint32_t addr) {
    asm volatile("ldmatrix.sync.aligned.m8n8.x4.shared.b16 {%0,%1,%2,%3}, [%4];"
                 : "=r"(r0), "=r"(r1), "=r"(r2), "=r"(r3) : "r"(addr));
}
__device__ __forceinline__ void mma16816(float* d, const uint32_t* a, const uint32_t* b) {
    asm volatile("mma.sync.aligned.m16n8k16.row.col.f32.bf16.bf16.f32 "
                 "{%0,%1,%2,%3}, {%4,%5,%6,%7}, {%8,%9}, {%0,%1,%2,%3};"
                 : "+f"(d[0]), "+f"(d[1]), "+f"(d[2]), "+f"(d[3])
                 : "r"(a[0]), "r"(a[1]), "r"(a[2]), "r"(a[3]), "r"(b[0]), "r"(b[1]));
}
__device__ __forceinline__ void cpasync16(uint32_t dst, const void* src) {
    asm volatile("cp.async.cg.shared.global [%0], [%1], 16;" :: "r"(dst), "l"(src));
}
#define CP_COMMIT() asm volatile("cp.async.commit_group;" ::: "memory")
__device__ __forceinline__ void cp_wait(int n) {
    switch (n) {
        case 0: asm volatile("cp.async.wait_group 0;" ::: "memory"); break;
        case 1: asm volatile("cp.async.wait_group 1;" ::: "memory"); break;
        case 2: asm volatile("cp.async.wait_group 2;" ::: "memory"); break;
        case 3: asm volatile("cp.async.wait_group 3;" ::: "memory"); break;
        case 4: asm volatile("cp.async.wait_group 4;" ::: "memory"); break;
        case 5: asm volatile("cp.async.wait_group 5;" ::: "memory"); break;
        case 6: asm volatile("cp.async.wait_group 6;" ::: "memory"); break;
        default: asm volatile("cp.async.wait_group 7;" ::: "memory"); break;
    }
}

__device__ __forceinline__ void stg_cs_f2(float* p, float a, float b) {
    asm volatile("st.global.cs.v2.f32 [%0], {%1, %2};" :: "l"(p), "f"(a), "f"(b) : "memory");
}

__device__ __forceinline__ unsigned fenc(float f) {
    unsigned u = __float_as_uint(f);
    return (u & 0x80000000u) ? ~u : (u | 0x80000000u);
}
__device__ __forceinline__ float fdec(unsigned u) {
    return __uint_as_float((u & 0x80000000u) ? (u ^ 0x80000000u) : ~u);
}

// ---------------- small kernels ----------------
__global__ void detect_kernel(const unsigned* __restrict__ yraw) {
    __shared__ unsigned red[256];
    unsigned acc = 0;
    for (int t = threadIdx.x; t < 2048; t += 256) acc |= yraw[2 * t + 1];
    red[threadIdx.x] = acc;
    __syncthreads();
    for (int s = 128; s; s >>= 1) {
        if (threadIdx.x < s) red[threadIdx.x] |= red[threadIdx.x + s];
        __syncthreads();
    }
    if (threadIdx.x == 0) g_is64 = (red[0] == 0) ? 1 : 0;
}

__global__ void prep_x_kernel(const float* __restrict__ x) {
    int idx = blockIdx.x * 256 + threadIdx.x;
    float v = x[idx];
    __nv_bfloat16 h = __float2bfloat16(v);
    g_xhi[idx] = h;
    g_xlo[idx] = __float2bfloat16(v - __bfloat162float(h));
}

__global__ void init_y_kernel(const void* __restrict__ yraw) {
    int i = blockIdx.x * 256 + threadIdx.x;
    if (i < NB) {
        g_y[i] = g_is64 ? (int)((const long long*)yraw)[i] : ((const int*)yraw)[i];
        g_minpos[i] = fenc(__int_as_float(0x7f800000));
        g_maxneg[i] = fenc(__int_as_float(0xff800000));
    }
}

// ============================================================================
// Pass 1: super-row triangular GEMM. CTA owns i-blocks {2a, 2a+1} (A resident,
// 136 KB) and a <=3-tile j-segment. Each B tile (single-buffered, 8 k-chunk
// cp.async groups pipelined under i-block-0's MMAs) serves both i-blocks.
// Stores S tile-blocked; row mining persistent in regs; column mining via
// register partials accumulated over both i-blocks -> tables -> reduce.
// ============================================================================
__global__ void __launch_bounds__(512, 1) pass1_kernel() {
    extern __shared__ char smem[];
    const uint32_t sb = smem_u32(smem);
    const int tid = threadIdx.x;
    const int w = tid >> 5, l = tid & 31;

    // segment decode
    int rem = blockIdx.x, a = 0;
    for (;;) {
        const int ns = (64 - 2 * a + SEGJ - 1) / SEGJ;
        if (rem < ns) break;
        rem -= ns;
        a++;
    }
    const int j0 = 2 * a + rem * SEGJ;
    const int j1 = (j0 + SEGJ < NTILE) ? j0 + SEGJ : NTILE;

    // ---- prologue: load A (both blocks, hi+lo) + yis, one commit group ----
    {
        const int arow = tid >> 2;
        const int aq = tid & 3;
#pragma unroll
        for (int st = 0; st < 4; st++) {
            const int bi = st >> 1, part = st & 1;
            const __nv_bfloat16* sp_ = part ? g_xlo : g_xhi;
            const char* src = (const char*)(sp_ + (size_t)((2 * a + bi) * TILE + arow) * ND)
                              + aq * 64;
            const uint32_t dst = sb + SM_A + st * ATS + arow * KPB + aq * 64;
#pragma unroll
            for (int c = 0; c < 4; c++) cpasync16(dst + c * 16, src + c * 16);
        }
        if (tid < 64) cpasync16(sb + SM_YIS + tid * 16, g_y + 2 * a * TILE + tid * 4);
        CP_COMMIT();
    }

    // warp/thread geometry: 4x4 warps of 32x32 tiles
    const int wr = (w & 3) * 32;
    const int wc = (w >> 2) * 32;
    const int gq = l >> 3, lr = l & 7;
    const int q = l >> 2;
    const int e2 = (l & 3) * 2;
    const uint32_t aoff = (uint32_t)((gq & 1) * 8 + lr) * KPB + (uint32_t)(gq >> 1) * 16;
    const uint32_t boff = (uint32_t)((gq >> 1) * 8 + lr) * KPB + (uint32_t)(gq & 1) * 16;

    // B loader decode
    const int lpart = tid >> 8;
    const int lrow = (tid >> 1) & 127;
    const int lhalf = tid & 1;
    const __nv_bfloat16* srcp = lpart ? g_xlo : g_xhi;

    float mp[8], mn[8];   // [bi*4 + k4]
#pragma unroll
    for (int k = 0; k < 8; k++) {
        mp[k] = __int_as_float(0x7f800000);
        mn[k] = __int_as_float(0xff800000);
    }

    for (int jt = j0; jt < j1; jt++) {
        __syncthreads();   // everyone done with previous B + tables

        // issue B chunks: 8 groups, 512 x 16B each (hi+lo interleaved by tid)
        {
            const char* bsrc = (const char*)(srcp + (size_t)(jt * TILE + lrow) * ND)
                               + lhalf * 16;
            const uint32_t bdst = sb + SM_B + lpart * ATS + lrow * KPB + lhalf * 16;
#pragma unroll
            for (int kc = 0; kc < 8; kc++) {
                cpasync16(bdst + kc * 32, bsrc + kc * 32);
                if (kc == 0 && tid < 32)
                    cpasync16(sb + SM_YJS + tid * 16, g_y + jt * TILE + tid * 4);
                CP_COMMIT();
            }
        }

        // per-jt column-mining partials (accumulated over both i-blocks)
        float pmin[8], pmax[8];
#pragma unroll
        for (int c = 0; c < 8; c++) {
            pmin[c] = __int_as_float(0x7f800000);
            pmax[c] = __int_as_float(0xff800000);
        }

#pragma unroll
        for (int bi = 0; bi < 2; bi++) {
            const int it = 2 * a + bi;
            if (it > jt) continue;   // only jt==2a skips bi=1

            const uint32_t aHi = sb + SM_A + bi * 2 * ATS;
            const uint32_t aLo = aHi + ATS;
            const uint32_t bHi = sb + SM_B;
            const uint32_t bLo = bHi + ATS;

            float acc[2][4][4];
#pragma unroll
            for (int mi = 0; mi < 2; mi++)
#pragma unroll
                for (int ni = 0; ni < 4; ni++)
#pragma unroll
                    for (int d = 0; d < 4; d++) acc[mi][ni][d] = 0.f;

#pragma unroll
            for (int kc = 0; kc < 8; kc++) {
                if (bi == 0) {
                    cp_wait(7 - kc);
                    __syncthreads();
                }
                const uint32_t ka = (uint32_t)kc * 32;
                uint32_t ah[2][4], al[2][4], bh[4][2], bl[4][2];
#pragma unroll
                for (int mi = 0; mi < 2; mi++) {
                    uint32_t o = (uint32_t)(wr + mi * 16) * KPB + aoff + ka;
                    ldsm4(ah[mi][0], ah[mi][1], ah[mi][2], ah[mi][3], aHi + o);
                    ldsm4(al[mi][0], al[mi][1], al[mi][2], al[mi][3], aLo + o);
                }
#pragma unroll
                for (int nq = 0; nq < 2; nq++) {
                    uint32_t o = (uint32_t)(wc + nq * 16) * KPB + boff + ka;
                    ldsm4(bh[nq * 2][0], bh[nq * 2][1], bh[nq * 2 + 1][0], bh[nq * 2 + 1][1],
                          bHi + o);
                    ldsm4(bl[nq * 2][0], bl[nq * 2][1], bl[nq * 2 + 1][0], bl[nq * 2 + 1][1],
                          bLo + o);
                }
#pragma unroll
                for (int mi = 0; mi < 2; mi++)
#pragma unroll
                    for (int ni = 0; ni < 4; ni++) {
                        mma16816(acc[mi][ni], ah[mi], bh[ni]);
                        mma16816(acc[mi][ni], ah[mi], bl[ni]);
                        mma16816(acc[mi][ni], al[mi], bh[ni]);
                    }
            }

            // ---- epilogue: blocked store + row mining + column partials ----
            const int* yis = (const int*)(smem + SM_YIS) + bi * 128;
            const int* yjs = (const int*)(smem + SM_YJS);
            const int stripbase = (129 * it - it * it) / 2;
            float* tbase = g_S + (size_t)(stripbase + (jt - it)) * (TILE * TILE);
            const bool offd = (it != jt);
#pragma unroll
            for (int mi = 0; mi < 2; mi++)
#pragma unroll
                for (int h = 0; h < 2; h++) {
                    const int ridx = mi * 2 + h;
                    const int rowi = wr + mi * 16 + h * 8 + q;
                    const int rowg = it * TILE + rowi;
                    const int yi = yis[rowi];
                    float* srow = tbase + (size_t)rowi * TILE;
#pragma unroll
                    for (int ni = 0; ni < 4; ni++) {
                        const float s0 = acc[mi][ni][h * 2 + 0];
                        const float s1 = acc[mi][ni][h * 2 + 1];
                        const int col = wc + ni * 8 + e2;
                        stg_cs_f2(srow + col, s0, s1);
#pragma unroll
                        for (int e = 0; e < 2; e++) {
                            const float sv = e ? s1 : s0;
                            const int cc = ni * 2 + e;
                            const int yj = yjs[col + e];
                            if (yj == yi) {
                                if (jt * TILE + col + e != rowg)
                                    mp[bi * 4 + ridx] = fminf(mp[bi * 4 + ridx], sv);
                                if (offd) pmin[cc] = fminf(pmin[cc], sv);
                            } else {
                                mn[bi * 4 + ridx] = fmaxf(mn[bi * 4 + ridx], sv);
                                if (offd) pmax[cc] = fmaxf(pmax[cc], sv);
                            }
                        }
                    }
                }
        }

        // ---- column-mining flush (any off-diagonal contribution this jt) ----
        if (jt != 2 * a) {
#pragma unroll
            for (int c = 0; c < 8; c++) {
                pmin[c] = fminf(pmin[c], __shfl_xor_sync(0xffffffffu, pmin[c], 8));
                pmin[c] = fminf(pmin[c], __shfl_xor_sync(0xffffffffu, pmin[c], 16));
                pmax[c] = fmaxf(pmax[c], __shfl_xor_sync(0xffffffffu, pmax[c], 8));
                pmax[c] = fmaxf(pmax[c], __shfl_xor_sync(0xffffffffu, pmax[c], 16));
            }
            float* tmin = (float*)(smem + SM_TBL);
            float* tmax = tmin + 128 * CTS;
            if (l < 8) {
                const int slot = (w & 3) * 2 + (l >> 2);
#pragma unroll
                for (int ni = 0; ni < 4; ni++)
#pragma unroll
                    for (int e = 0; e < 2; e++) {
                        const int col = wc + ni * 8 + e2 + e;
                        tmin[col * CTS + slot] = pmin[ni * 2 + e];
                        tmax[col * CTS + slot] = pmax[ni * 2 + e];
                    }
            }
            __syncthreads();
            if (tid < 128) {
                const int col = tid;
                float cmp = __int_as_float(0x7f800000);
                float cmx = __int_as_float(0xff800000);
#pragma unroll
                for (int kk = 0; kk < 8; kk++) {
                    cmp = fminf(cmp, tmin[col * CTS + kk]);
                    cmx = fmaxf(cmx, tmax[col * CTS + kk]);
                }
                atomicMin(&g_minpos[jt * TILE + col], fenc(cmp));
                atomicMax(&g_maxneg[jt * TILE + col], fenc(cmx));
            }
        }
    }

    // ---- flush persistent row mining (both i-blocks) ----
#pragma unroll
    for (int bi = 0; bi < 2; bi++)
#pragma unroll
        for (int k4 = 0; k4 < 4; k4++) {
            float av = mp[bi * 4 + k4], bv = mn[bi * 4 + k4];
            av = fminf(av, __shfl_xor_sync(0xffffffffu, av, 1));
            av = fminf(av, __shfl_xor_sync(0xffffffffu, av, 2));
            bv = fmaxf(bv, __shfl_xor_sync(0xffffffffu, bv, 1));
            bv = fmaxf(bv, __shfl_xor_sync(0xffffffffu, bv, 2));
            if ((l & 3) == 0) {
                const int rowi = wr + (k4 >> 1) * 16 + (k4 & 1) * 8 + q;
                const int rowg = (2 * a + bi) * TILE + rowi;
                atomicMin(&g_minpos[rowg], fenc(av));
                atomicMax(&g_maxneg[rowg], fenc(bv));
            }
        }
}

// ============================================================================
// Pass 2: one CTA per upper tile (a,b). Register-fused: each element read
// ONCE; its exp value feeds BOTH row i and row j sums. Flags derived from
// sums (>0) downstream — all kept terms are strictly positive in fp32.
// ============================================================================
__global__ void __launch_bounds__(256) pass2_kernel() {
    __shared__ int yis[128], yjs_s[128];
    __shared__ float mpI[128], mxI[128], mpJ[128], mxJ[128];
    __shared__ float tps[128 * 9];
    __shared__ float tns[128 * 9];

    int rem = blockIdx.x, a = 0;
    while (true) {
        int c = NTILE - a;
        if (rem < c) break;
        rem -= c;
        a++;
    }
    const int b = a + rem;
    const int ib = a * TILE;
    const int jbb = b * TILE;
    const bool doCol = (a != b);

    const int tid = threadIdx.x;
    const int w = tid >> 5, l = tid & 31;

    if (tid < 128) {
        yis[tid] = g_y[ib + tid];
        mpI[tid] = fdec(g_minpos[ib + tid]);
        mxI[tid] = fdec(g_maxneg[ib + tid]);
    } else {
        const int t = tid - 128;
        yjs_s[t] = g_y[jbb + t];
        mpJ[t] = fdec(g_minpos[jbb + t]);
        mxJ[t] = fdec(g_maxneg[jbb + t]);
    }
    __syncthreads();

    int yj_[4];
    float mpJ_[4], mxJ_[4], psC[4], nsC[4];
#pragma unroll
    for (int e = 0; e < 4; e++) {
        const int col = l * 4 + e;
        yj_[e] = yjs_s[col];
        mpJ_[e] = mpJ[col];
        mxJ_[e] = mxJ[col];
        psC[e] = 0.f;
        nsC[e] = 0.f;
    }

    const float4* src = (const float4*)(g_S + (size_t)blockIdx.x * (TILE * TILE));

#pragma unroll 4
    for (int k = 0; k < 16; k++) {
        const int r = w + k * 8;
        const int i = ib + r;
        const int yi = yis[r];
        const float minp = mpI[r];
        const float maxn = mxI[r];
        float4 v = __ldcs(src + tid + k * 256);
        const float sv[4] = {v.x, v.y, v.z, v.w};
        float psR = 0.f, nsR = 0.f;
#pragma unroll
        for (int e = 0; e < 4; e++) {
            const float s = sv[e];
            const int jg = jbb + l * 4 + e;
            if (yj_[e] != yi) {
                const bool fR = (s + 0.1f > minp);
                const bool fC = doCol && (s + 0.1f > mpJ_[e]);
                if (fR || fC) {
                    const float ex = __expf(50.0f * (s - 1.0f));
                    if (fR) nsR += ex;
                    if (fC) nsC[e] += ex;
                }
            } else {
                const bool fR = (jg != i) && (s - 0.1f < maxn);
                const bool fC = doCol && (s - 0.1f < mxJ_[e]);
                if (fR || fC) {
                    const float ex = __expf(-2.0f * (s - 1.0f));
                    if (fR) psR += ex;
                    if (fC) psC[e] += ex;
                }
            }
        }
#pragma unroll
        for (int off = 16; off; off >>= 1) {
            psR += __shfl_xor_sync(0xffffffffu, psR, off);
            nsR += __shfl_xor_sync(0xffffffffu, nsR, off);
        }
        if (l == 0) {
            const size_t slot = (size_t)i * NTILE + b;
            g_psT[slot] = psR;
            g_nsT[slot] = nsR;
        }
    }

    if (doCol) {
#pragma unroll
        for (int e = 0; e < 4; e++) {
            const int col = l * 4 + e;
            tps[col * 9 + w] = psC[e];
            tns[col * 9 + w] = nsC[e];
        }
        __syncthreads();
        if (tid < 128) {
            const int col = tid;
            float ps = 0.f, ns = 0.f;
#pragma unroll
            for (int kk = 0; kk < 8; kk++) {
                ps += tps[col * 9 + kk];
                ns += tns[col * 9 + kk];
            }
            const size_t slot = (size_t)(jbb + col) * NTILE + a;
            g_psT[slot] = ps;
            g_nsT[slot] = ns;
        }
    }
}

// ============================================================================
// Row finalize: sum 64 per-tile partials; flags from positivity of sums.
// ============================================================================
__global__ void rowfinal_kernel() {
    const int i = blockIdx.x * 256 + threadIdx.x;
    float ps = 0.f, ns = 0.f;
    const size_t base = (size_t)i * NTILE;
#pragma unroll 8
    for (int t = 0; t < NTILE; t++) {
        ps += g_psT[base + t];
        ns += g_nsT[base + t];
    }
    int valid = (ps > 0.f && ns > 0.f) ? 1 : 0;
    g_row[i] = valid ? (0.5f * log1pf(ps) + 0.02f * log1pf(ns)) : 0.f;
    g_valid[i] = valid;
}

__global__ void __launch_bounds__(256) finalize_kernel(float* __restrict__ out) {
    __shared__ float ssum[256];
    __shared__ int scnt[256];
    float s = 0.f;
    int c = 0;
    for (int i = threadIdx.x; i < NB; i += 256) {
        s += g_row[i];
        c += g_valid[i];
    }
    ssum[threadIdx.x] = s;
    scnt[threadIdx.x] = c;
    __syncthreads();
    for (int k = 128; k; k >>= 1) {
        if (threadIdx.x < k) {
            ssum[threadIdx.x] += ssum[threadIdx.x + k];
            scnt[threadIdx.x] += scnt[threadIdx.x + k];
        }
        __syncthreads();
    }
    if (threadIdx.x == 0) {
        int n = scnt[0];
        out[0] = (n > 0) ? (ssum[0] / (float)n) : 0.f;
    }
}

extern "C" void kernel_launch(void* const* d_in, const int* in_sizes, int n_in,
                              void* d_out, int out_size) {
    const float* x = (const float*)d_in[0];
    const void* y = d_in[1];

    cudaFuncSetAttribute(pass1_kernel, cudaFuncAttributeMaxDynamicSharedMemorySize, SMEM_TOTAL);

    detect_kernel<<<1, 256>>>((const unsigned*)y);
    prep_x_kernel<<<NB * ND / 256, 256>>>(x);
    init_y_kernel<<<NB / 256, 256>>>(y);

    pass1_kernel<<<NSEG1, 512, SMEM_TOTAL>>>();

    pass2_kernel<<<NTRI, 256>>>();
    rowfinal_kernel<<<NB / 256, 256>>>();
    finalize_kernel<<<1, 256>>>((float*)d_out);
}

// round 13
// speedup vs baseline: 1.1313x; 1.1313x over previous
#include <cuda_runtime.h>
#include <cuda_bf16.h>
#include <cstdint>
#include <cstddef>

#define NB 8192
#define ND 128
#define TILE 128
#define NTILE (NB / TILE)       // 64
#define NTRI 2080               // upper-triangular tiles
#define NCHUNK 1056             // 2-tile chunks over the triangle

#define KPB 272                 // row pitch in bytes (136 halves): conflict-free ldmatrix
#define ATS 34816               // one 128x128 bf16 tile with pitch 272
#define SM_YIS 0
#define SM_YJS 512              // 2 x 512B (double-buffered with B)
#define SM_A   2048             // hi at +0, lo at +ATS (persistent per chunk)
#define SM_B   (SM_A + 2 * ATS) // 2 bufs x (hi,lo)
#define SM_TBL (SM_B + 4 * ATS) // column tables: 2 x 128 x 9 floats
#define SMEM_TOTAL (SM_TBL + 9216)   // 220160 B
#define CTS 9

__device__ __align__(16) float g_S[(size_t)NTRI * TILE * TILE];  // 136 MB, tile-blocked
__device__ __align__(16) __nv_bfloat16 g_xhi[(size_t)NB * ND];
__device__ __align__(16) __nv_bfloat16 g_xlo[(size_t)NB * ND];
__device__ unsigned g_minpos[NB];
__device__ unsigned g_maxneg[NB];
__device__ int g_y[NB];
__device__ float g_psT[(size_t)NB * NTILE];   // per (row, tile) partials
__device__ float g_nsT[(size_t)NB * NTILE];
__device__ float g_row[NB];
__device__ int   g_valid[NB];
__device__ int   g_is64;

// ---------------- helpers ----------------
__device__ __forceinline__ uint32_t smem_u32(const void* p) {
    uint32_t a;
    asm("{ .reg .u64 t; cvta.to.shared.u64 t, %1; cvt.u32.u64 %0, t; }" : "=r"(a) : "l"(p));
    return a;
}
__device__ __forceinline__ void ldsm4(uint32_t& r0, uint32_t& r1, uint32_t& r2, uint32_t& r3,
                                      uint32_t addr) {
    asm volatile("ldmatrix.sync.aligned.m8n8.x4.shared.b16 {%0,%1,%2,%3}, [%4];"
                 : "=r"(r0), "=r"(r1), "=r"(r2), "=r"(r3) : "r"(addr));
}
__device__ __forceinline__ void mma16816(float* d, const uint32_t* a, const uint32_t* b) {
    asm volatile("mma.sync.aligned.m16n8k16.row.col.f32.bf16.bf16.f32 "
                 "{%0,%1,%2,%3}, {%4,%5,%6,%7}, {%8,%9}, {%0,%1,%2,%3};"
                 : "+f"(d[0]), "+f"(d[1]), "+f"(d[2]), "+f"(d[3])
                 : "r"(a[0]), "r"(a[1]), "r"(a[2]), "r"(a[3]), "r"(b[0]), "r"(b[1]));
}
__device__ __forceinline__ void cpasync16(uint32_t dst, const void* src) {
    asm volatile("cp.async.cg.shared.global [%0], [%1], 16;" :: "r"(dst), "l"(src));
}
#define CP_COMMIT() asm volatile("cp.async.commit_group;" ::: "memory")
#define CP_WAIT0()  asm volatile("cp.async.wait_group 0;" ::: "memory")

__device__ __forceinline__ void stg_cs_f2(float* p, float a, float b) {
    asm volatile("st.global.cs.v2.f32 [%0], {%1, %2};" :: "l"(p), "f"(a), "f"(b) : "memory");
}

__device__ __forceinline__ unsigned fenc(float f) {
    unsigned u = __float_as_uint(f);
    return (u & 0x80000000u) ? ~u : (u | 0x80000000u);
}
__device__ __forceinline__ float fdec(unsigned u) {
    return __uint_as_float((u & 0x80000000u) ? (u ^ 0x80000000u) : ~u);
}

// ---------------- small kernels ----------------
__global__ void detect_kernel(const unsigned* __restrict__ yraw) {
    __shared__ unsigned red[256];
    unsigned acc = 0;
    for (int t = threadIdx.x; t < 2048; t += 256) acc |= yraw[2 * t + 1];
    red[threadIdx.x] = acc;
    __syncthreads();
    for (int s = 128; s; s >>= 1) {
        if (threadIdx.x < s) red[threadIdx.x] |= red[threadIdx.x + s];
        __syncthreads();
    }
    if (threadIdx.x == 0) g_is64 = (red[0] == 0) ? 1 : 0;
}

__global__ void prep_x_kernel(const float* __restrict__ x) {
    int idx = blockIdx.x * 256 + threadIdx.x;
    float v = x[idx];
    __nv_bfloat16 h = __float2bfloat16(v);
    g_xhi[idx] = h;
    g_xlo[idx] = __float2bfloat16(v - __bfloat162float(h));
}

__global__ void init_y_kernel(const void* __restrict__ yraw) {
    int i = blockIdx.x * 256 + threadIdx.x;
    if (i < NB) {
        g_y[i] = g_is64 ? (int)((const long long*)yraw)[i] : ((const int*)yraw)[i];
        g_minpos[i] = fenc(__int_as_float(0x7f800000));
        g_maxneg[i] = fenc(__int_as_float(0xff800000));
    }
}

// ============================================================================
// Pass 1 (R11-proven config): triangular GEMM in 2-tile chunks. Stores S into
// TILE-BLOCKED layout (tile-contiguous 64KB). Row mining in persistent regs;
// column mining via register partials -> shfl -> tables -> 128-thread reduce.
// ============================================================================
__global__ void __launch_bounds__(512, 1) pass1_kernel() {
    extern __shared__ char smem[];
    const uint32_t sb = smem_u32(smem);
    const int tid = threadIdx.x;
    const int w = tid >> 5, l = tid & 31;

    // chunk decode: it, jt0, cnt
    int rem = blockIdx.x, it = 0;
    while (true) {
        int c = (65 - it) >> 1;
        if (rem < c) break;
        rem -= c;
        it++;
    }
    const int jt0 = it + rem * 2;
    const int cnt = (jt0 + 1 <= NTILE - 1) ? 2 : 1;
    const int ib = it * TILE;
    const int stripbase = (129 * it - it * it) / 2;   // triangular tile index base

    // loader decode
    const int lpart = tid >> 8;           // 0: hi, 1: lo
    const int lrow = (tid >> 1) & 127;
    const int lhalf = tid & 1;
    const __nv_bfloat16* srcp = lpart ? g_xlo : g_xhi;

    // prologue: A(hi+lo) + yis + B(jt0) + yjs0, one commit group
    {
        const char* sA = (const char*)(srcp + (size_t)(ib + lrow) * ND) + lhalf * 128;
        const uint32_t dA = sb + SM_A + lpart * ATS + lrow * KPB + lhalf * 128;
#pragma unroll
        for (int c = 0; c < 8; c++) cpasync16(dA + c * 16, sA + c * 16);
        const int jB = jt0 * TILE;
        const char* sB = (const char*)(srcp + (size_t)(jB + lrow) * ND) + lhalf * 128;
        const uint32_t dB = sb + SM_B + lpart * ATS + lrow * KPB + lhalf * 128;
#pragma unroll
        for (int c = 0; c < 8; c++) cpasync16(dB + c * 16, sB + c * 16);
        if (tid < 32) cpasync16(sb + SM_YIS + tid * 16, g_y + ib + tid * 4);
        else if (tid < 64) cpasync16(sb + SM_YJS + (tid - 32) * 16, g_y + jB + (tid - 32) * 4);
        CP_COMMIT();
    }

    // warp/thread geometry: 4x4 warps of 32x32 tiles
    const int wr = (w & 3) * 32;
    const int wc = (w >> 2) * 32;
    const int gq = l >> 3, lr = l & 7;
    const int q = l >> 2;
    const int e2 = (l & 3) * 2;
    const uint32_t aoff = (uint32_t)((gq & 1) * 8 + lr) * KPB + (uint32_t)(gq >> 1) * 16;
    const uint32_t boff = (uint32_t)((gq >> 1) * 8 + lr) * KPB + (uint32_t)(gq & 1) * 16;
    const uint32_t aHi = sb + SM_A;
    const uint32_t aLo = sb + SM_A + ATS;

    int rowg[4], yrow[4];
    float mp[4], mn[4];
#pragma unroll
    for (int k4 = 0; k4 < 4; k4++) {
        mp[k4] = __int_as_float(0x7f800000);
        mn[k4] = __int_as_float(0xff800000);
    }

    for (int idx = 0; idx < cnt; idx++) {
        const int buf = idx & 1;
        const int jt = jt0 + idx;
        const int jb = jt * TILE;
        float* tbase = g_S + (size_t)(stripbase + (jt - it)) * (TILE * TILE);
        CP_WAIT0();
        __syncthreads();  // B[buf]+yjs[buf] ready; tables consumed

        if (idx == 0) {
#pragma unroll
            for (int k4 = 0; k4 < 4; k4++) {
                const int rowi = wr + (k4 >> 1) * 16 + (k4 & 1) * 8 + q;
                rowg[k4] = ib + rowi;
                yrow[k4] = ((const int*)(smem + SM_YIS))[rowi];
            }
        }

        // prefetch next B tile
        if (idx + 1 < cnt) {
            const int jn = (jt + 1) * TILE;
            const char* sB = (const char*)(srcp + (size_t)(jn + lrow) * ND) + lhalf * 128;
            const uint32_t dB = sb + SM_B + (1 - buf) * 2 * ATS + lpart * ATS +
                                lrow * KPB + lhalf * 128;
#pragma unroll
            for (int c = 0; c < 8; c++) cpasync16(dB + c * 16, sB + c * 16);
            if (tid < 32)
                cpasync16(sb + SM_YJS + (1 - buf) * 512 + tid * 16, g_y + jn + tid * 4);
            CP_COMMIT();
        }

        float acc[2][4][4];
#pragma unroll
        for (int mi = 0; mi < 2; mi++)
#pragma unroll
            for (int ni = 0; ni < 4; ni++)
#pragma unroll
                for (int d = 0; d < 4; d++) acc[mi][ni][d] = 0.f;

        const uint32_t bHi = sb + SM_B + buf * 2 * ATS;
        const uint32_t bLo = bHi + ATS;

#pragma unroll
        for (int kc = 0; kc < 8; kc++) {
            const uint32_t ka = (uint32_t)kc * 32;
            uint32_t ah[2][4], al[2][4], bh[4][2], bl[4][2];
#pragma unroll
            for (int mi = 0; mi < 2; mi++) {
                uint32_t o = (uint32_t)(wr + mi * 16) * KPB + aoff + ka;
                ldsm4(ah[mi][0], ah[mi][1], ah[mi][2], ah[mi][3], aHi + o);
                ldsm4(al[mi][0], al[mi][1], al[mi][2], al[mi][3], aLo + o);
            }
#pragma unroll
            for (int nq = 0; nq < 2; nq++) {
                uint32_t o = (uint32_t)(wc + nq * 16) * KPB + boff + ka;
                ldsm4(bh[nq * 2][0], bh[nq * 2][1], bh[nq * 2 + 1][0], bh[nq * 2 + 1][1], bHi + o);
                ldsm4(bl[nq * 2][0], bl[nq * 2][1], bl[nq * 2 + 1][0], bl[nq * 2 + 1][1], bLo + o);
            }
#pragma unroll
            for (int mi = 0; mi < 2; mi++)
#pragma unroll
                for (int ni = 0; ni < 4; ni++) {
                    mma16816(acc[mi][ni], ah[mi], bh[ni]);
                    mma16816(acc[mi][ni], ah[mi], bl[ni]);
                    mma16816(acc[mi][ni], al[mi], bh[ni]);
                }
        }

        // ---- epilogue: blocked store + row mining ----
        const int* yjs = (const int*)(smem + SM_YJS + buf * 512);
#pragma unroll
        for (int mi = 0; mi < 2; mi++)
#pragma unroll
            for (int h = 0; h < 2; h++) {
                const int ridx = mi * 2 + h;
                float* srow = tbase + (size_t)(rowg[ridx] - ib) * TILE;
#pragma unroll
                for (int ni = 0; ni < 4; ni++) {
                    const float s0 = acc[mi][ni][h * 2 + 0];
                    const float s1 = acc[mi][ni][h * 2 + 1];
                    const int col = wc + ni * 8 + e2;
                    stg_cs_f2(srow + col, s0, s1);
#pragma unroll
                    for (int e = 0; e < 2; e++) {
                        const float sv = e ? s1 : s0;
                        const int jj = jb + col + e;
                        const int yj = yjs[col + e];
                        if (yj == yrow[ridx]) {
                            if (jj != rowg[ridx]) mp[ridx] = fminf(mp[ridx], sv);
                        } else {
                            mn[ridx] = fmaxf(mn[ridx], sv);
                        }
                    }
                }
            }

        // ---- column mining (off-diagonal only) ----
        if (jt != it) {
            float pmin[8], pmax[8];
#pragma unroll
            for (int c = 0; c < 8; c++) {
                pmin[c] = __int_as_float(0x7f800000);
                pmax[c] = __int_as_float(0xff800000);
            }
#pragma unroll
            for (int mi = 0; mi < 2; mi++)
#pragma unroll
                for (int h = 0; h < 2; h++) {
                    const int ridx = mi * 2 + h;
#pragma unroll
                    for (int ni = 0; ni < 4; ni++)
#pragma unroll
                        for (int e = 0; e < 2; e++) {
                            const float sv = acc[mi][ni][h * 2 + e];
                            const int c = ni * 2 + e;
                            const int yj = yjs[wc + ni * 8 + e2 + e];
                            if (yj == yrow[ridx]) pmin[c] = fminf(pmin[c], sv);
                            else pmax[c] = fmaxf(pmax[c], sv);
                        }
                }
#pragma unroll
            for (int c = 0; c < 8; c++) {
                pmin[c] = fminf(pmin[c], __shfl_xor_sync(0xffffffffu, pmin[c], 8));
                pmin[c] = fminf(pmin[c], __shfl_xor_sync(0xffffffffu, pmin[c], 16));
                pmax[c] = fmaxf(pmax[c], __shfl_xor_sync(0xffffffffu, pmax[c], 8));
                pmax[c] = fmaxf(pmax[c], __shfl_xor_sync(0xffffffffu, pmax[c], 16));
            }
            float* tmin = (float*)(smem + SM_TBL);
            float* tmax = tmin + 128 * CTS;
            if (l < 8) {
                const int slot = (w & 3) * 2 + (l >> 2);
#pragma unroll
                for (int ni = 0; ni < 4; ni++)
#pragma unroll
                    for (int e = 0; e < 2; e++) {
                        const int col = wc + ni * 8 + e2 + e;
                        tmin[col * CTS + slot] = pmin[ni * 2 + e];
                        tmax[col * CTS + slot] = pmax[ni * 2 + e];
                    }
            }
            __syncthreads();
            if (tid < 128) {
                const int col = tid;
                float cmp = __int_as_float(0x7f800000);
                float cmx = __int_as_float(0xff800000);
#pragma unroll
                for (int kk = 0; kk < 8; kk++) {
                    cmp = fminf(cmp, tmin[col * CTS + kk]);
                    cmx = fmaxf(cmx, tmax[col * CTS + kk]);
                }
                atomicMin(&g_minpos[jb + col], fenc(cmp));
                atomicMax(&g_maxneg[jb + col], fenc(cmx));
            }
        }
    }

    // flush persistent row mining
#pragma unroll
    for (int k4 = 0; k4 < 4; k4++) {
        float a = mp[k4], bv = mn[k4];
        a = fminf(a, __shfl_xor_sync(0xffffffffu, a, 1));
        a = fminf(a, __shfl_xor_sync(0xffffffffu, a, 2));
        bv = fmaxf(bv, __shfl_xor_sync(0xffffffffu, bv, 1));
        bv = fmaxf(bv, __shfl_xor_sync(0xffffffffu, bv, 2));
        if ((l & 3) == 0) {
            atomicMin(&g_minpos[rowg[k4]], fenc(a));
            atomicMax(&g_maxneg[rowg[k4]], fenc(bv));
        }
    }
}

// ============================================================================
// Pass 2 (R12-proven, flag-free): one CTA per upper tile (a,b). Each element
// read ONCE; its exp value feeds BOTH row i and row j sums. Validity derived
// from sum positivity downstream (all kept terms strictly positive in fp32).
// ============================================================================
__global__ void __launch_bounds__(256) pass2_kernel() {
    __shared__ int yis[128], yjs_s[128];
    __shared__ float mpI[128], mxI[128], mpJ[128], mxJ[128];
    __shared__ float tps[128 * 9];
    __shared__ float tns[128 * 9];

    int rem = blockIdx.x, a = 0;
    while (true) {
        int c = NTILE - a;
        if (rem < c) break;
        rem -= c;
        a++;
    }
    const int b = a + rem;
    const int ib = a * TILE;
    const int jbb = b * TILE;
    const bool doCol = (a != b);

    const int tid = threadIdx.x;
    const int w = tid >> 5, l = tid & 31;

    if (tid < 128) {
        yis[tid] = g_y[ib + tid];
        mpI[tid] = fdec(g_minpos[ib + tid]);
        mxI[tid] = fdec(g_maxneg[ib + tid]);
    } else {
        const int t = tid - 128;
        yjs_s[t] = g_y[jbb + t];
        mpJ[t] = fdec(g_minpos[jbb + t]);
        mxJ[t] = fdec(g_maxneg[jbb + t]);
    }
    __syncthreads();

    int yj_[4];
    float mpJ_[4], mxJ_[4], psC[4], nsC[4];
#pragma unroll
    for (int e = 0; e < 4; e++) {
        const int col = l * 4 + e;
        yj_[e] = yjs_s[col];
        mpJ_[e] = mpJ[col];
        mxJ_[e] = mxJ[col];
        psC[e] = 0.f;
        nsC[e] = 0.f;
    }

    const float4* src = (const float4*)(g_S + (size_t)blockIdx.x * (TILE * TILE));

#pragma unroll 4
    for (int k = 0; k < 16; k++) {
        const int r = w + k * 8;
        const int i = ib + r;
        const int yi = yis[r];
        const float minp = mpI[r];
        const float maxn = mxI[r];
        float4 v = __ldcs(src + tid + k * 256);
        const float sv[4] = {v.x, v.y, v.z, v.w};
        float psR = 0.f, nsR = 0.f;
#pragma unroll
        for (int e = 0; e < 4; e++) {
            const float s = sv[e];
            const int jg = jbb + l * 4 + e;
            if (yj_[e] != yi) {
                const bool fR = (s + 0.1f > minp);
                const bool fC = doCol && (s + 0.1f > mpJ_[e]);
                if (fR || fC) {
                    const float ex = __expf(50.0f * (s - 1.0f));
                    if (fR) nsR += ex;
                    if (fC) nsC[e] += ex;
                }
            } else {
                const bool fR = (jg != i) && (s - 0.1f < maxn);
                const bool fC = doCol && (s - 0.1f < mxJ_[e]);
                if (fR || fC) {
                    const float ex = __expf(-2.0f * (s - 1.0f));
                    if (fR) psR += ex;
                    if (fC) psC[e] += ex;
                }
            }
        }
#pragma unroll
        for (int off = 16; off; off >>= 1) {
            psR += __shfl_xor_sync(0xffffffffu, psR, off);
            nsR += __shfl_xor_sync(0xffffffffu, nsR, off);
        }
        if (l == 0) {
            const size_t slot = (size_t)i * NTILE + b;
            g_psT[slot] = psR;
            g_nsT[slot] = nsR;
        }
    }

    if (doCol) {
#pragma unroll
        for (int e = 0; e < 4; e++) {
            const int col = l * 4 + e;
            tps[col * 9 + w] = psC[e];
            tns[col * 9 + w] = nsC[e];
        }
        __syncthreads();
        if (tid < 128) {
            const int col = tid;
            float ps = 0.f, ns = 0.f;
#pragma unroll
            for (int kk = 0; kk < 8; kk++) {
                ps += tps[col * 9 + kk];
                ns += tns[col * 9 + kk];
            }
            const size_t slot = (size_t)(jbb + col) * NTILE + a;
            g_psT[slot] = ps;
            g_nsT[slot] = ns;
        }
    }
}

// ============================================================================
// Row finalize: sum 64 per-tile partials; flags from positivity of sums.
// ============================================================================
__global__ void rowfinal_kernel() {
    const int i = blockIdx.x * 256 + threadIdx.x;
    float ps = 0.f, ns = 0.f;
    const size_t base = (size_t)i * NTILE;
#pragma unroll 8
    for (int t = 0; t < NTILE; t++) {
        ps += g_psT[base + t];
        ns += g_nsT[base + t];
    }
    int valid = (ps > 0.f && ns > 0.f) ? 1 : 0;
    g_row[i] = valid ? (0.5f * log1pf(ps) + 0.02f * log1pf(ns)) : 0.f;
    g_valid[i] = valid;
}

__global__ void __launch_bounds__(256) finalize_kernel(float* __restrict__ out) {
    __shared__ float ssum[256];
    __shared__ int scnt[256];
    float s = 0.f;
    int c = 0;
    for (int i = threadIdx.x; i < NB; i += 256) {
        s += g_row[i];
        c += g_valid[i];
    }
    ssum[threadIdx.x] = s;
    scnt[threadIdx.x] = c;
    __syncthreads();
    for (int k = 128; k; k >>= 1) {
        if (threadIdx.x < k) {
            ssum[threadIdx.x] += ssum[threadIdx.x + k];
            scnt[threadIdx.x] += scnt[threadIdx.x + k];
        }
        __syncthreads();
    }
    if (threadIdx.x == 0) {
        int n = scnt[0];
        out[0] = (n > 0) ? (ssum[0] / (float)n) : 0.f;
    }
}

extern "C" void kernel_launch(void* const* d_in, const int* in_sizes, int n_in,
                              void* d_out, int out_size) {
    const float* x = (const float*)d_in[0];
    const void* y = d_in[1];

    cudaFuncSetAttribute(pass1_kernel, cudaFuncAttributeMaxDynamicSharedMemorySize, SMEM_TOTAL);

    detect_kernel<<<1, 256>>>((const unsigned*)y);
    prep_x_kernel<<<NB * ND / 256, 256>>>(x);
    init_y_kernel<<<NB / 256, 256>>>(y);

    pass1_kernel<<<NCHUNK, 512, SMEM_TOTAL>>>();

    pass2_kernel<<<NTRI, 256>>>();
    rowfinal_kernel<<<NB / 256, 256>>>();
    finalize_kernel<<<1, 256>>>((float*)d_out);
}

// round 16
// speedup vs baseline: 1.5107x; 1.3354x over previous
#include <cuda_runtime.h>
#include <cuda_fp16.h>
#include <cstdint>
#include <cstddef>

#define NB 8192
#define ND 128
#define TILE 128
#define NTILE (NB / TILE)       // 64
#define NTRI 2080               // upper-triangular tiles
#define NCHUNK 1056             // 2-tile chunks over the triangle

#define KPB 272                 // row pitch in bytes (136 halves): conflict-free ldmatrix
#define ATS 34816               // one 128x128 fp16 tile with pitch 272
#define SM_YIS 0
#define SM_YJS 512              // 2 x 512B (double-buffered with B)
#define SM_TBL 1536             // 2 x 128 x 9 floats = 9216
#define SM_A   10752            // 1 x ATS (persistent per chunk)
#define SM_B   (SM_A + ATS)     // 2 bufs
#define SMEM_TOTAL (SM_B + 2 * ATS)   // 115200 B
#define CTS 9

__device__ __align__(16) float g_S[(size_t)NTRI * TILE * TILE];  // 136 MB, tile-blocked
__device__ __align__(16) __half g_xh[(size_t)NB * ND];
__device__ unsigned g_minpos[NB];
__device__ unsigned g_maxneg[NB];
__device__ int g_y[NB];
__device__ float g_psT[(size_t)NB * NTILE];   // per (row, tile) partials
__device__ float g_nsT[(size_t)NB * NTILE];
__device__ float g_row[NB];
__device__ int   g_valid[NB];
__device__ int   g_is64;

// ---------------- helpers ----------------
__device__ __forceinline__ uint32_t smem_u32(const void* p) {
    uint32_t a;
    asm("{ .reg .u64 t; cvta.to.shared.u64 t, %1; cvt.u32.u64 %0, t; }" : "=r"(a) : "l"(p));
    return a;
}
__device__ __forceinline__ void ldsm4(uint32_t& r0, uint32_t& r1, uint32_t& r2, uint32_t& r3,
                                      uint32_t addr) {
    asm volatile("ldmatrix.sync.aligned.m8n8.x4.shared.b16 {%0,%1,%2,%3}, [%4];"
                 : "=r"(r0), "=r"(r1), "=r"(r2), "=r"(r3) : "r"(addr));
}
__device__ __forceinline__ void mma16816h(float* d, const uint32_t* a, const uint32_t* b) {
    asm volatile("mma.sync.aligned.m16n8k16.row.col.f32.f16.f16.f32 "
                 "{%0,%1,%2,%3}, {%4,%5,%6,%7}, {%8,%9}, {%0,%1,%2,%3};"
                 : "+f"(d[0]), "+f"(d[1]), "+f"(d[2]), "+f"(d[3])
                 : "r"(a[0]), "r"(a[1]), "r"(a[2]), "r"(a[3]), "r"(b[0]), "r"(b[1]));
}
__device__ __forceinline__ void cpasync16(uint32_t dst, const void* src) {
    asm volatile("cp.async.cg.shared.global [%0], [%1], 16;" :: "r"(dst), "l"(src));
}
#define CP_COMMIT() asm volatile("cp.async.commit_group;" ::: "memory")
#define CP_WAIT0()  asm volatile("cp.async.wait_group 0;" ::: "memory")

__device__ __forceinline__ void stg_cs_f2(float* p, float a, float b) {
    asm volatile("st.global.cs.v2.f32 [%0], {%1, %2};" :: "l"(p), "f"(a), "f"(b) : "memory");
}

__device__ __forceinline__ unsigned fenc(float f) {
    unsigned u = __float_as_uint(f);
    return (u & 0x80000000u) ? ~u : (u | 0x80000000u);
}
__device__ __forceinline__ float fdec(unsigned u) {
    return __uint_as_float((u & 0x80000000u) ? (u ^ 0x80000000u) : ~u);
}

// ---------------- small kernels ----------------
__global__ void detect_kernel(const unsigned* __restrict__ yraw) {
    __shared__ unsigned red[256];
    unsigned acc = 0;
    for (int t = threadIdx.x; t < 2048; t += 256) acc |= yraw[2 * t + 1];
    red[threadIdx.x] = acc;
    __syncthreads();
    for (int s = 128; s; s >>= 1) {
        if (threadIdx.x < s) red[threadIdx.x] |= red[threadIdx.x + s];
        __syncthreads();
    }
    if (threadIdx.x == 0) g_is64 = (red[0] == 0) ? 1 : 0;
}

__global__ void prep_x_kernel(const float* __restrict__ x) {
    int idx = blockIdx.x * 256 + threadIdx.x;
    g_xh[idx] = __float2half(x[idx]);
}

__global__ void init_y_kernel(const void* __restrict__ yraw) {
    int i = blockIdx.x * 256 + threadIdx.x;
    if (i < NB) {
        g_y[i] = g_is64 ? (int)((const long long*)yraw)[i] : ((const int*)yraw)[i];
        g_minpos[i] = fenc(__int_as_float(0x7f800000));
        g_maxneg[i] = fenc(__int_as_float(0xff800000));
    }
}

// ============================================================================
// Pass 1: triangular fp16 GEMM (single product, fp32 accum) in 2-tile chunks.
// Stores S into TILE-BLOCKED layout. Row mining in persistent regs; column
// mining via register partials -> shfl -> tables -> 128-thread reduce.
// ============================================================================
__global__ void __launch_bounds__(512, 1) pass1_kernel() {
    extern __shared__ char smem[];
    const uint32_t sb = smem_u32(smem);
    const int tid = threadIdx.x;
    const int w = tid >> 5, l = tid & 31;

    // chunk decode: it, jt0, cnt
    int rem = blockIdx.x, it = 0;
    while (true) {
        int c = (65 - it) >> 1;
        if (rem < c) break;
        rem -= c;
        it++;
    }
    const int jt0 = it + rem * 2;
    const int cnt = (jt0 + 1 <= NTILE - 1) ? 2 : 1;
    const int ib = it * TILE;
    const int stripbase = (129 * it - it * it) / 2;   // triangular tile index base

    // loader decode: thread -> (row, 64B quarter)
    const int lrow = tid >> 2;
    const int lq = tid & 3;

    // prologue: A + yis + B(jt0) + yjs0, one commit group
    {
        const char* sA = (const char*)(g_xh + (size_t)(ib + lrow) * ND) + lq * 64;
        const uint32_t dA = sb + SM_A + lrow * KPB + lq * 64;
#pragma unroll
        for (int c = 0; c < 4; c++) cpasync16(dA + c * 16, sA + c * 16);
        const int jB = jt0 * TILE;
        const char* sB = (const char*)(g_xh + (size_t)(jB + lrow) * ND) + lq * 64;
        const uint32_t dB = sb + SM_B + lrow * KPB + lq * 64;
#pragma unroll
        for (int c = 0; c < 4; c++) cpasync16(dB + c * 16, sB + c * 16);
        if (tid < 32) cpasync16(sb + SM_YIS + tid * 16, g_y + ib + tid * 4);
        else if (tid < 64) cpasync16(sb + SM_YJS + (tid - 32) * 16, g_y + jB + (tid - 32) * 4);
        CP_COMMIT();
    }

    // warp/thread geometry: 4x4 warps of 32x32 tiles
    const int wr = (w & 3) * 32;
    const int wc = (w >> 2) * 32;
    const int gq = l >> 3, lr = l & 7;
    const int q = l >> 2;
    const int e2 = (l & 3) * 2;
    const uint32_t aoff = (uint32_t)((gq & 1) * 8 + lr) * KPB + (uint32_t)(gq >> 1) * 16;
    const uint32_t boff = (uint32_t)((gq >> 1) * 8 + lr) * KPB + (uint32_t)(gq & 1) * 16;
    const uint32_t aBase = sb + SM_A;

    int rowg[4], yrow[4];
    float mp[4], mn[4];
#pragma unroll
    for (int k4 = 0; k4 < 4; k4++) {
        mp[k4] = __int_as_float(0x7f800000);
        mn[k4] = __int_as_float(0xff800000);
    }

    for (int idx = 0; idx < cnt; idx++) {
        const int buf = idx & 1;
        const int jt = jt0 + idx;
        const int jb = jt * TILE;
        float* tbase = g_S + (size_t)(stripbase + (jt - it)) * (TILE * TILE);
        CP_WAIT0();
        __syncthreads();  // B[buf]+yjs[buf] ready; tables consumed

        if (idx == 0) {
#pragma unroll
            for (int k4 = 0; k4 < 4; k4++) {
                const int rowi = wr + (k4 >> 1) * 16 + (k4 & 1) * 8 + q;
                rowg[k4] = ib + rowi;
                yrow[k4] = ((const int*)(smem + SM_YIS))[rowi];
            }
        }

        // prefetch next B tile
        if (idx + 1 < cnt) {
            const int jn = (jt + 1) * TILE;
            const char* sB = (const char*)(g_xh + (size_t)(jn + lrow) * ND) + lq * 64;
            const uint32_t dB = sb + SM_B + (1 - buf) * ATS + lrow * KPB + lq * 64;
#pragma unroll
            for (int c = 0; c < 4; c++) cpasync16(dB + c * 16, sB + c * 16);
            if (tid < 32)
                cpasync16(sb + SM_YJS + (1 - buf) * 512 + tid * 16, g_y + jn + tid * 4);
            CP_COMMIT();
        }

        float acc[2][4][4];
#pragma unroll
        for (int mi = 0; mi < 2; mi++)
#pragma unroll
            for (int ni = 0; ni < 4; ni++)
#pragma unroll
                for (int d = 0; d < 4; d++) acc[mi][ni][d] = 0.f;

        const uint32_t bBase = sb + SM_B + buf * ATS;

#pragma unroll
        for (int kc = 0; kc < 8; kc++) {
            const uint32_t ka = (uint32_t)kc * 32;
            uint32_t ah[2][4], bh[4][2];
#pragma unroll
            for (int mi = 0; mi < 2; mi++) {
                uint32_t o = (uint32_t)(wr + mi * 16) * KPB + aoff + ka;
                ldsm4(ah[mi][0], ah[mi][1], ah[mi][2], ah[mi][3], aBase + o);
            }
#pragma unroll
            for (int nq = 0; nq < 2; nq++) {
                uint32_t o = (uint32_t)(wc + nq * 16) * KPB + boff + ka;
                ldsm4(bh[nq * 2][0], bh[nq * 2][1], bh[nq * 2 + 1][0], bh[nq * 2 + 1][1],
                      bBase + o);
            }
#pragma unroll
            for (int mi = 0; mi < 2; mi++)
#pragma unroll
                for (int ni = 0; ni < 4; ni++)
                    mma16816h(acc[mi][ni], ah[mi], bh[ni]);
        }

        // ---- epilogue: blocked store + row mining ----
        const int* yjs = (const int*)(smem + SM_YJS + buf * 512);
#pragma unroll
        for (int mi = 0; mi < 2; mi++)
#pragma unroll
            for (int h = 0; h < 2; h++) {
                const int ridx = mi * 2 + h;
                float* srow = tbase + (size_t)(rowg[ridx] - ib) * TILE;
#pragma unroll
                for (int ni = 0; ni < 4; ni++) {
                    const float s0 = acc[mi][ni][h * 2 + 0];
                    const float s1 = acc[mi][ni][h * 2 + 1];
                    const int col = wc + ni * 8 + e2;
                    stg_cs_f2(srow + col, s0, s1);
#pragma unroll
                    for (int e = 0; e < 2; e++) {
                        const float sv = e ? s1 : s0;
                        const int jj = jb + col + e;
                        const int yj = yjs[col + e];
                        if (yj == yrow[ridx]) {
                            if (jj != rowg[ridx]) mp[ridx] = fminf(mp[ridx], sv);
                        } else {
                            mn[ridx] = fmaxf(mn[ridx], sv);
                        }
                    }
                }
            }

        // ---- column mining (off-diagonal only) ----
        if (jt != it) {
            float pmin[8], pmax[8];
#pragma unroll
            for (int c = 0; c < 8; c++) {
                pmin[c] = __int_as_float(0x7f800000);
                pmax[c] = __int_as_float(0xff800000);
            }
#pragma unroll
            for (int mi = 0; mi < 2; mi++)
#pragma unroll
                for (int h = 0; h < 2; h++) {
                    const int ridx = mi * 2 + h;
#pragma unroll
                    for (int ni = 0; ni < 4; ni++)
#pragma unroll
                        for (int e = 0; e < 2; e++) {
                            const float sv = acc[mi][ni][h * 2 + e];
                            const int c = ni * 2 + e;
                            const int yj = yjs[wc + ni * 8 + e2 + e];
                            if (yj == yrow[ridx]) pmin[c] = fminf(pmin[c], sv);
                            else pmax[c] = fmaxf(pmax[c], sv);
                        }
                }
#pragma unroll
            for (int c = 0; c < 8; c++) {
                pmin[c] = fminf(pmin[c], __shfl_xor_sync(0xffffffffu, pmin[c], 8));
                pmin[c] = fminf(pmin[c], __shfl_xor_sync(0xffffffffu, pmin[c], 16));
                pmax[c] = fmaxf(pmax[c], __shfl_xor_sync(0xffffffffu, pmax[c], 8));
                pmax[c] = fmaxf(pmax[c], __shfl_xor_sync(0xffffffffu, pmax[c], 16));
            }
            float* tmin = (float*)(smem + SM_TBL);
            float* tmax = tmin + 128 * CTS;
            if (l < 8) {
                const int slot = (w & 3) * 2 + (l >> 2);
#pragma unroll
                for (int ni = 0; ni < 4; ni++)
#pragma unroll
                    for (int e = 0; e < 2; e++) {
                        const int col = wc + ni * 8 + e2 + e;
                        tmin[col * CTS + slot] = pmin[ni * 2 + e];
                        tmax[col * CTS + slot] = pmax[ni * 2 + e];
                    }
            }
            __syncthreads();
            if (tid < 128) {
                const int col = tid;
                float cmp = __int_as_float(0x7f800000);
                float cmx = __int_as_float(0xff800000);
#pragma unroll
                for (int kk = 0; kk < 8; kk++) {
                    cmp = fminf(cmp, tmin[col * CTS + kk]);
                    cmx = fmaxf(cmx, tmax[col * CTS + kk]);
                }
                atomicMin(&g_minpos[jb + col], fenc(cmp));
                atomicMax(&g_maxneg[jb + col], fenc(cmx));
            }
        }
    }

    // flush persistent row mining
#pragma unroll
    for (int k4 = 0; k4 < 4; k4++) {
        float a = mp[k4], bv = mn[k4];
        a = fminf(a, __shfl_xor_sync(0xffffffffu, a, 1));
        a = fminf(a, __shfl_xor_sync(0xffffffffu, a, 2));
        bv = fmaxf(bv, __shfl_xor_sync(0xffffffffu, bv, 1));
        bv = fmaxf(bv, __shfl_xor_sync(0xffffffffu, bv, 2));
        if ((l & 3) == 0) {
            atomicMin(&g_minpos[rowg[k4]], fenc(a));
            atomicMax(&g_maxneg[rowg[k4]], fenc(bv));
        }
    }
}

// ============================================================================
// Pass 2 (flag-free): one CTA per upper tile (a,b). Each element read ONCE;
// its exp value feeds BOTH row i and row j sums. Validity from sum positivity.
// ============================================================================
__global__ void __launch_bounds__(256) pass2_kernel() {
    __shared__ int yis[128], yjs_s[128];
    __shared__ float mpI[128], mxI[128], mpJ[128], mxJ[128];
    __shared__ float tps[128 * 9];
    __shared__ float tns[128 * 9];

    int rem = blockIdx.x, a = 0;
    while (true) {
        int c = NTILE - a;
        if (rem < c) break;
        rem -= c;
        a++;
    }
    const int b = a + rem;
    const int ib = a * TILE;
    const int jbb = b * TILE;
    const bool doCol = (a != b);

    const int tid = threadIdx.x;
    const int w = tid >> 5, l = tid & 31;

    if (tid < 128) {
        yis[tid] = g_y[ib + tid];
        mpI[tid] = fdec(g_minpos[ib + tid]);
        mxI[tid] = fdec(g_maxneg[ib + tid]);
    } else {
        const int t = tid - 128;
        yjs_s[t] = g_y[jbb + t];
        mpJ[t] = fdec(g_minpos[jbb + t]);
        mxJ[t] = fdec(g_maxneg[jbb + t]);
    }
    __syncthreads();

    int yj_[4];
    float mpJ_[4], mxJ_[4], psC[4], nsC[4];
#pragma unroll
    for (int e = 0; e < 4; e++) {
        const int col = l * 4 + e;
        yj_[e] = yjs_s[col];
        mpJ_[e] = mpJ[col];
        mxJ_[e] = mxJ[col];
        psC[e] = 0.f;
        nsC[e] = 0.f;
    }

    const float4* src = (const float4*)(g_S + (size_t)blockIdx.x * (TILE * TILE));

#pragma unroll 4
    for (int k = 0; k < 16; k++) {
        const int r = w + k * 8;
        const int i = ib + r;
        const int yi = yis[r];
        const float minp = mpI[r];
        const float maxn = mxI[r];
        float4 v = __ldcs(src + tid + k * 256);
        const float sv[4] = {v.x, v.y, v.z, v.w};
        float psR = 0.f, nsR = 0.f;
#pragma unroll
        for (int e = 0; e < 4; e++) {
            const float s = sv[e];
            const int jg = jbb + l * 4 + e;
            if (yj_[e] != yi) {
                const bool fR = (s + 0.1f > minp);
                const bool fC = doCol && (s + 0.1f > mpJ_[e]);
                if (fR || fC) {
                    const float ex = __expf(50.0f * (s - 1.0f));
                    if (fR) nsR += ex;
                    if (fC) nsC[e] += ex;
                }
            } else {
                const bool fR = (jg != i) && (s - 0.1f < maxn);
                const bool fC = doCol && (s - 0.1f < mxJ_[e]);
                if (fR || fC) {
                    const float ex = __expf(-2.0f * (s - 1.0f));
                    if (fR) psR += ex;
                    if (fC) psC[e] += ex;
                }
            }
        }
#pragma unroll
        for (int off = 16; off; off >>= 1) {
            psR += __shfl_xor_sync(0xffffffffu, psR, off);
            nsR += __shfl_xor_sync(0xffffffffu, nsR, off);
        }
        if (l == 0) {
            const size_t slot = (size_t)i * NTILE + b;
            g_psT[slot] = psR;
            g_nsT[slot] = nsR;
        }
    }

    if (doCol) {
#pragma unroll
        for (int e = 0; e < 4; e++) {
            const int col = l * 4 + e;
            tps[col * 9 + w] = psC[e];
            tns[col * 9 + w] = nsC[e];
        }
        __syncthreads();
        if (tid < 128) {
            const int col = tid;
            float ps = 0.f, ns = 0.f;
#pragma unroll
            for (int kk = 0; kk < 8; kk++) {
                ps += tps[col * 9 + kk];
                ns += tns[col * 9 + kk];
            }
            const size_t slot = (size_t)(jbb + col) * NTILE + a;
            g_psT[slot] = ps;
            g_nsT[slot] = ns;
        }
    }
}

// ============================================================================
// Row finalize: sum 64 per-tile partials; flags from positivity of sums.
// ============================================================================
__global__ void rowfinal_kernel() {
    const int i = blockIdx.x * 256 + threadIdx.x;
    float ps = 0.f, ns = 0.f;
    const size_t base = (size_t)i * NTILE;
#pragma unroll 8
    for (int t = 0; t < NTILE; t++) {
        ps += g_psT[base + t];
        ns += g_nsT[base + t];
    }
    int valid = (ps > 0.f && ns > 0.f) ? 1 : 0;
    g_row[i] = valid ? (0.5f * log1pf(ps) + 0.02f * log1pf(ns)) : 0.f;
    g_valid[i] = valid;
}

__global__ void __launch_bounds__(256) finalize_kernel(float* __restrict__ out) {
    __shared__ float ssum[256];
    __shared__ int scnt[256];
    float s = 0.f;
    int c = 0;
    for (int i = threadIdx.x; i < NB; i += 256) {
        s += g_row[i];
        c += g_valid[i];
    }
    ssum[threadIdx.x] = s;
    scnt[threadIdx.x] = c;
    __syncthreads();
    for (int k = 128; k; k >>= 1) {
        if (threadIdx.x < k) {
            ssum[threadIdx.x] += ssum[threadIdx.x + k];
            scnt[threadIdx.x] += scnt[threadIdx.x + k];
        }
        __syncthreads();
    }
    if (threadIdx.x == 0) {
        int n = scnt[0];
        out[0] = (n > 0) ? (ssum[0] / (float)n) : 0.f;
    }
}

extern "C" void kernel_launch(void* const* d_in, const int* in_sizes, int n_in,
                              void* d_out, int out_size) {
    const float* x = (const float*)d_in[0];
    const void* y = d_in[1];

    cudaFuncSetAttribute(pass1_kernel, cudaFuncAttributeMaxDynamicSharedMemorySize, SMEM_TOTAL);

    detect_kernel<<<1, 256>>>((const unsigned*)y);
    prep_x_kernel<<<NB * ND / 256, 256>>>(x);
    init_y_kernel<<<NB / 256, 256>>>(y);

    pass1_kernel<<<NCHUNK, 512, SMEM_TOTAL>>>();

    pass2_kernel<<<NTRI, 256>>>();
    rowfinal_kernel<<<NB / 256, 256>>>();
    finalize_kernel<<<1, 256>>>((float*)d_out);
}